// round 6
// baseline (speedup 1.0000x reference)
#include <cuda_runtime.h>
#include <cuda_bf16.h>
#include <cstdint>

// -(1/B) * sum(preds_t * log(preds_s)),  B = 4096, C = 1000  (n = 4,096,000)
// TMA (cp.async.bulk) pipelined reduction:
//   n_vec = 1,024,000 float4 = 500 CTAs x 2048 float4/CTA (contiguous chunk)
//   4 stages of 512 float4 per array, 2 smem buffers, mbarrier expect_tx.

#define NTHR      256
#define NBLK_EX   500
#define STAGE_V4  512                    // float4 per array per stage
#define STAGE_B   (STAGE_V4 * 16)        // 8192 bytes
#define NSTAGES   4
#define CHUNK_V4  (STAGE_V4 * NSTAGES)   // 2048 float4 per array per CTA
#define MAXBLK    2048

__device__ float g_partials[MAXBLK];
__device__ unsigned int g_ticket;        // zero-init; reset by last block each call

__device__ __forceinline__ uint32_t smem_u32(const void* p) {
    uint32_t a;
    asm("{ .reg .u64 t; cvta.to.shared.u64 t, %1; cvt.u32.u64 %0, t; }" : "=r"(a) : "l"(p));
    return a;
}

__device__ __forceinline__ void mbar_init(uint32_t mbar, uint32_t count) {
    asm volatile("mbarrier.init.shared::cta.b64 [%0], %1;" :: "r"(mbar), "r"(count) : "memory");
}
__device__ __forceinline__ void mbar_expect_tx(uint32_t mbar, uint32_t tx) {
    asm volatile("mbarrier.arrive.expect_tx.shared::cta.b64 _, [%0], %1;" :: "r"(mbar), "r"(tx) : "memory");
}
__device__ __forceinline__ void mbar_wait(uint32_t mbar, uint32_t parity) {
    asm volatile(
        "{\n\t"
        ".reg .pred P;\n\t"
        "WL_%=:\n\t"
        "mbarrier.try_wait.parity.acquire.cta.shared::cta.b64 P, [%0], %1, 0x989680;\n\t"
        "@P bra.uni WD_%=;\n\t"
        "bra.uni WL_%=;\n\t"
        "WD_%=:\n\t"
        "}" :: "r"(mbar), "r"(parity) : "memory");
}
__device__ __forceinline__ void bulk_g2s(uint32_t dst, const void* src, uint32_t bytes, uint32_t mbar) {
    asm volatile(
        "cp.async.bulk.shared::cta.global.mbarrier::complete_tx::bytes [%0], [%1], %2, [%3];"
        :: "r"(dst), "l"(src), "r"(bytes), "r"(mbar) : "memory");
}

__device__ __forceinline__ float block_reduce(float acc, float* warp_sums)
{
    #pragma unroll
    for (int off = 16; off > 0; off >>= 1)
        acc += __shfl_xor_sync(0xFFFFFFFFu, acc, off);

    int lane = threadIdx.x & 31;
    int wid  = threadIdx.x >> 5;
    if (lane == 0) warp_sums[wid] = acc;
    __syncthreads();

    float v = 0.0f;
    if (wid == 0) {
        v = (lane < NTHR / 32) ? warp_sums[lane] : 0.0f;
        #pragma unroll
        for (int off = 4; off > 0; off >>= 1)
            v += __shfl_xor_sync(0xFFFFFFFFu, v, off);
    }
    return v;   // valid in warp 0 lane 0
}

__device__ __forceinline__ void finish(float acc, float inv_B, float* out, int nblk)
{
    __shared__ float warp_sums[NTHR / 32];
    float bsum = block_reduce(acc, warp_sums);

    __shared__ bool is_last;
    if (threadIdx.x == 0) {
        g_partials[blockIdx.x] = bsum;
        __threadfence();
        unsigned int ticket = atomicAdd(&g_ticket, 1u);
        is_last = (ticket == (unsigned int)(nblk - 1));
    }
    __syncthreads();

    if (is_last) {
        float a = 0.0f;
        for (int i = threadIdx.x; i < nblk; i += NTHR)
            a += g_partials[i];
        __syncthreads();
        float total = block_reduce(a, warp_sums);
        if (threadIdx.x == 0) {
            out[0] = -total * inv_B;
            g_ticket = 0;                   // reset for next graph replay
        }
    }
}

__global__ __launch_bounds__(NTHR) void tma_reduce(
    const float4* __restrict__ s4, const float4* __restrict__ t4,
    float inv_B, float* __restrict__ out)
{
    __shared__ alignas(128) float4 buf_s[2][STAGE_V4];
    __shared__ alignas(128) float4 buf_t[2][STAGE_V4];
    __shared__ alignas(8) unsigned long long mbar_store[2];

    const uint32_t mb0 = smem_u32(&mbar_store[0]);
    const uint32_t mb1 = smem_u32(&mbar_store[1]);
    const uint32_t bs0 = smem_u32(&buf_s[0][0]);
    const uint32_t bs1 = smem_u32(&buf_s[1][0]);
    const uint32_t bt0 = smem_u32(&buf_t[0][0]);
    const uint32_t bt1 = smem_u32(&buf_t[1][0]);

    const long base = (long)blockIdx.x * CHUNK_V4;

    if (threadIdx.x == 0) {
        mbar_init(mb0, 1);
        mbar_init(mb1, 1);
    }
    __syncthreads();

    // Prologue: issue stages 0 (buf 0) and 1 (buf 1)
    if (threadIdx.x == 0) {
        mbar_expect_tx(mb0, 2 * STAGE_B);
        bulk_g2s(bs0, s4 + base, STAGE_B, mb0);
        bulk_g2s(bt0, t4 + base, STAGE_B, mb0);
        mbar_expect_tx(mb1, 2 * STAGE_B);
        bulk_g2s(bs1, s4 + base + STAGE_V4, STAGE_B, mb1);
        bulk_g2s(bt1, t4 + base + STAGE_V4, STAGE_B, mb1);
    }

    float acc = 0.0f;

    #pragma unroll
    for (int it = 0; it < NSTAGES; ++it) {
        const int b = it & 1;
        const int p = (it >> 1) & 1;
        mbar_wait(b ? mb1 : mb0, p);

        float4 sv0 = buf_s[b][threadIdx.x];
        float4 sv1 = buf_s[b][threadIdx.x + NTHR];
        float4 tv0 = buf_t[b][threadIdx.x];
        float4 tv1 = buf_t[b][threadIdx.x + NTHR];

        acc += tv0.x * __logf(sv0.x);
        acc += tv0.y * __logf(sv0.y);
        acc += tv0.z * __logf(sv0.z);
        acc += tv0.w * __logf(sv0.w);
        acc += tv1.x * __logf(sv1.x);
        acc += tv1.y * __logf(sv1.y);
        acc += tv1.z * __logf(sv1.z);
        acc += tv1.w * __logf(sv1.w);

        __syncthreads();   // buffer b fully consumed by all threads

        if (threadIdx.x == 0 && it + 2 < NSTAGES) {
            const int ns = it + 2;
            const uint32_t mb = b ? mb1 : mb0;
            mbar_expect_tx(mb, 2 * STAGE_B);
            bulk_g2s(b ? bs1 : bs0, s4 + base + (long)ns * STAGE_V4, STAGE_B, mb);
            bulk_g2s(b ? bt1 : bt0, t4 + base + (long)ns * STAGE_V4, STAGE_B, mb);
        }
    }

    finish(acc, inv_B, out, NBLK_EX);
}

// Generic fallback (any n), grid-stride. Only used if shape isn't exact-cover.
__global__ __launch_bounds__(NTHR) void fused_reduce_generic(
    const float* __restrict__ s, const float* __restrict__ t,
    int n, float inv_B, float* __restrict__ out, int nblk)
{
    int n_vec = n / 4;
    int tail0 = n_vec * 4;
    const float4* s4 = reinterpret_cast<const float4*>(s);
    const float4* t4 = reinterpret_cast<const float4*>(t);

    float acc = 0.0f;
    int stride = nblk * NTHR;
    for (int i = blockIdx.x * NTHR + threadIdx.x; i < n_vec; i += stride) {
        float4 sv = s4[i];
        float4 tv = t4[i];
        acc += tv.x * __logf(sv.x);
        acc += tv.y * __logf(sv.y);
        acc += tv.z * __logf(sv.z);
        acc += tv.w * __logf(sv.w);
    }
    if (blockIdx.x == 0) {
        for (int i = tail0 + threadIdx.x; i < n; i += NTHR)
            acc += t[i] * __logf(s[i]);
    }

    finish(acc, inv_B, out, nblk);
}

extern "C" void kernel_launch(void* const* d_in, const int* in_sizes, int n_in,
                              void* d_out, int out_size)
{
    const float* s = (const float*)d_in[0];  // preds_s
    const float* t = (const float*)d_in[1];  // preds_t
    float* out = (float*)d_out;

    int n = in_sizes[0];
    float inv_B = (n == 4096000) ? (1.0f / 4096.0f) : (1000.0f / (float)n);

    int n_vec = n / 4;

    if ((n % 4 == 0) && (n_vec == NBLK_EX * CHUNK_V4)) {
        tma_reduce<<<NBLK_EX, NTHR>>>(
            reinterpret_cast<const float4*>(s),
            reinterpret_cast<const float4*>(t),
            inv_B, out);
    } else {
        int nblk = 1024;
        fused_reduce_generic<<<nblk, NTHR>>>(s, t, n, inv_B, out, nblk);
    }
}